// round 2
// baseline (speedup 1.0000x reference)
#include <cuda_runtime.h>

#define NN 100000
#define NE 1200000
#define D 64
#define NL 3
#define NG 256
#define RH 128
#define RO 32
#define INDIM (D*NL)   // 192

// ---------------- scratch (device globals; no allocation allowed) ----------
__device__ int   d_deg[NN];
__device__ int   d_rowptr[NN + 1];
__device__ int   d_cursor[NN];
__device__ int   d_col[NE];
__device__ int   d_bsum[128];
__device__ int   d_gstart[NG + 1];
__device__ float d_h0[NN * D];
__device__ float d_h1[NN * D];
__device__ float d_g[NG * INDIM];

// ---------------- CSR build ------------------------------------------------
__global__ void k_zero_deg() {
    int i = blockIdx.x * blockDim.x + threadIdx.x;
    if (i < NN) d_deg[i] = 0;
}

__global__ void k_hist(const int* __restrict__ dst) {
    int e = blockIdx.x * blockDim.x + threadIdx.x;
    if (e < NE) atomicAdd(&d_deg[dst[e]], 1);
}

// CHUNK = 1024 elements per block, 256 threads x 4 items
__global__ void k_blocksum() {
    __shared__ int sh[256];
    int b = blockIdx.x, tid = threadIdx.x;
    int base = b * 1024 + tid * 4;
    int s = 0;
#pragma unroll
    for (int i = 0; i < 4; i++) {
        int idx = base + i;
        if (idx < NN) s += d_deg[idx];
    }
    sh[tid] = s;
    __syncthreads();
    for (int off = 128; off > 0; off >>= 1) {
        if (tid < off) sh[tid] += sh[tid + off];
        __syncthreads();
    }
    if (tid == 0) d_bsum[b] = sh[0];
}

__global__ void k_scan_bsum(int nb) {
    if (threadIdx.x == 0 && blockIdx.x == 0) {
        int acc = 0;
        for (int i = 0; i < nb; i++) { int v = d_bsum[i]; d_bsum[i] = acc; acc += v; }
        d_rowptr[NN] = acc;
    }
}

__global__ void k_scanfinal() {
    __shared__ int sh[256];
    int b = blockIdx.x, tid = threadIdx.x;
    int base = b * 1024 + tid * 4;
    int v[4];
    int s = 0;
#pragma unroll
    for (int i = 0; i < 4; i++) {
        int idx = base + i;
        v[i] = (idx < NN) ? d_deg[idx] : 0;
        s += v[i];
    }
    sh[tid] = s;
    __syncthreads();
    // inclusive Hillis-Steele scan over thread sums
    for (int off = 1; off < 256; off <<= 1) {
        int t = 0;
        if (tid >= off) t = sh[tid - off];
        __syncthreads();
        if (tid >= off) sh[tid] += t;
        __syncthreads();
    }
    int run = d_bsum[b] + sh[tid] - s;  // exclusive offset for this thread
#pragma unroll
    for (int i = 0; i < 4; i++) {
        int idx = base + i;
        if (idx < NN) {
            d_rowptr[idx] = run;
            d_cursor[idx] = run;
            run += v[i];
        }
    }
}

__global__ void k_scatter(const int* __restrict__ src, const int* __restrict__ dst) {
    int e = blockIdx.x * blockDim.x + threadIdx.x;
    if (e < NE) {
        int dn = dst[e];
        int p = atomicAdd(&d_cursor[dn], 1);
        d_col[p] = src[e];
    }
}

__global__ void k_gstart(const int* __restrict__ gids) {
    int g = blockIdx.x * blockDim.x + threadIdx.x;
    if (g > NG) return;
    if (g == NG) { d_gstart[NG] = NN; return; }
    // lower_bound over sorted gids
    int lo = 0, hi = NN;
    while (lo < hi) {
        int mid = (lo + hi) >> 1;
        if (gids[mid] < g) lo = mid + 1; else hi = mid;
    }
    d_gstart[g] = lo;
}

// ---------------- fused GIN layer: aggregate + (1+eps)h + matvec + relu ----
// 8 warps/block, 1 warp per node. Each lane owns dims {lane, lane+32} for the
// matvec output and a float2 slice for aggregation.
__global__ void __launch_bounds__(256) k_gin_layer(
    const float* __restrict__ hin, float* __restrict__ hout,
    const float* __restrict__ gin_W, const float* __restrict__ gin_b,
    const float* __restrict__ eps, int layer)
{
    __shared__ float Ws[D * D];      // 16 KB
    __shared__ float bs[D];
    __shared__ float zbuf[8][D];

    int tid = threadIdx.x;
    int w = tid >> 5;
    int lane = tid & 31;

    const float* Wg = gin_W + layer * (D * D);
    for (int i = tid; i < D * D; i += 256) Ws[i] = Wg[i];
    if (tid < D) bs[tid] = gin_b[layer * D + tid];
    float epsv = 1.0f + eps[layer];
    __syncthreads();

    int node = blockIdx.x * 8 + w;   // grid sized so node < NN always

    // aggregate: z = (1+eps)*h[node] + sum_{s in N(node)} h[s]
    const float2* hrow = (const float2*)(hin + (size_t)node * D);
    float2 acc = hrow[lane];
    acc.x *= epsv; acc.y *= epsv;

    int beg = d_rowptr[node], end = d_rowptr[node + 1];
    for (int e0 = beg; e0 < end; e0 += 32) {
        int idx = e0 + lane;
        int sn = (idx < end) ? d_col[idx] : 0;
        int cnt = min(32, end - e0);
        int j = 0;
        for (; j + 4 <= cnt; j += 4) {
            int s0 = __shfl_sync(0xffffffffu, sn, j + 0);
            int s1 = __shfl_sync(0xffffffffu, sn, j + 1);
            int s2 = __shfl_sync(0xffffffffu, sn, j + 2);
            int s3 = __shfl_sync(0xffffffffu, sn, j + 3);
            float2 v0 = ((const float2*)(hin + (size_t)s0 * D))[lane];
            float2 v1 = ((const float2*)(hin + (size_t)s1 * D))[lane];
            float2 v2 = ((const float2*)(hin + (size_t)s2 * D))[lane];
            float2 v3 = ((const float2*)(hin + (size_t)s3 * D))[lane];
            acc.x += v0.x + v1.x + v2.x + v3.x;
            acc.y += v0.y + v1.y + v2.y + v3.y;
        }
        for (; j < cnt; j++) {
            int sj = __shfl_sync(0xffffffffu, sn, j);
            float2 v = ((const float2*)(hin + (size_t)sj * D))[lane];
            acc.x += v.x; acc.y += v.y;
        }
    }

    zbuf[w][lane * 2]     = acc.x;
    zbuf[w][lane * 2 + 1] = acc.y;
    __syncwarp();

    // matvec: out[j] = relu(b[j] + sum_k z[k] * W[k][j])
    float o0 = bs[lane];
    float o1 = bs[lane + 32];
#pragma unroll
    for (int k = 0; k < D; k++) {
        float zk = zbuf[w][k];
        o0 += zk * Ws[k * D + lane];
        o1 += zk * Ws[k * D + lane + 32];
    }
    float* orow = hout + (size_t)node * D;
    orow[lane]      = fmaxf(o0, 0.0f);
    orow[lane + 32] = fmaxf(o1, 0.0f);
}

// ---------------- per-graph segment sum (no atomics: gids sorted) ---------
// one block per graph; 256 threads = 64 dims x 4 node partitions
__global__ void k_graph_accum(const float* __restrict__ h, int layer) {
    __shared__ float red[256];
    int b = blockIdx.x;
    int tid = threadIdx.x;
    int dim = tid & 63;
    int part = tid >> 6;
    int gs = d_gstart[b], ge = d_gstart[b + 1];
    float s = 0.0f;
    for (int i = gs + part; i < ge; i += 4)
        s += h[(size_t)i * D + dim];
    red[tid] = s;
    __syncthreads();
    if (part == 0) {
        float tot = red[dim] + red[64 + dim] + red[128 + dim] + red[192 + dim];
        d_g[b * INDIM + layer * D + dim] = tot;
    }
}

// ---------------- readout MLP ---------------------------------------------
__global__ void k_mlp(const float* __restrict__ W1, const float* __restrict__ b1,
                      const float* __restrict__ W2, const float* __restrict__ b2,
                      float* __restrict__ out)
{
    __shared__ float gv[INDIM];
    __shared__ float hid[RH];
    int b = blockIdx.x;
    int tid = threadIdx.x;   // 128 threads
    for (int i = tid; i < INDIM; i += RH) gv[i] = d_g[b * INDIM + i];
    __syncthreads();
    float a = b1[tid];
#pragma unroll 8
    for (int k = 0; k < INDIM; k++)
        a += gv[k] * W1[k * RH + tid];
    hid[tid] = fmaxf(a, 0.0f);
    __syncthreads();
    if (tid < RO) {
        float o = b2[tid];
#pragma unroll 8
        for (int k = 0; k < RH; k++)
            o += hid[k] * W2[k * RO + tid];
        out[b * RO + tid] = o;
    }
}

// ---------------- launch ---------------------------------------------------
extern "C" void kernel_launch(void* const* d_in, const int* in_sizes, int n_in,
                              void* d_out, int out_size)
{
    const float* x      = (const float*)d_in[0];
    const float* gin_W  = (const float*)d_in[1];
    const float* gin_b  = (const float*)d_in[2];
    const float* eps    = (const float*)d_in[3];
    const float* r_W1   = (const float*)d_in[4];
    const float* r_b1   = (const float*)d_in[5];
    const float* r_W2   = (const float*)d_in[6];
    const float* r_b2   = (const float*)d_in[7];
    const int*   src    = (const int*)d_in[8];
    const int*   dst    = (const int*)d_in[9];
    const int*   gids   = (const int*)d_in[10];
    float* out = (float*)d_out;

    const int NB_SCAN = (NN + 1023) / 1024;  // 98

    // get addresses of double buffers as symbols within kernels; host passes
    // them via cudaGetSymbolAddress-free path: use a small static table of
    // pointers obtained from a helper kernel is overkill — instead use
    // cudaGetSymbolAddress (not an allocation).
    static float* h0p = nullptr;
    static float* h1p = nullptr;
    if (!h0p) {
        cudaGetSymbolAddress((void**)&h0p, d_h0);
        cudaGetSymbolAddress((void**)&h1p, d_h1);
    }

    // CSR build
    k_zero_deg<<<(NN + 255) / 256, 256>>>();
    k_hist<<<(NE + 255) / 256, 256>>>(dst);
    k_blocksum<<<NB_SCAN, 256>>>();
    k_scan_bsum<<<1, 32>>>(NB_SCAN);
    k_scanfinal<<<NB_SCAN, 256>>>();
    k_scatter<<<(NE + 255) / 256, 256>>>(src, dst);
    k_gstart<<<2, 256>>>(gids);

    // GIN layers (fused agg + linear + relu) and per-graph readout sums
    const float* hin = x;
    float* bufs[2] = { h0p, h1p };
    for (int l = 0; l < NL; l++) {
        float* hout = bufs[l & 1];
        k_gin_layer<<<NN / 8, 256>>>(hin, hout, gin_W, gin_b, eps, l);
        k_graph_accum<<<NG, 256>>>(hout, l);
        hin = hout;
    }

    // head MLP
    k_mlp<<<NG, RH>>>(r_W1, r_b1, r_W2, r_b2, out);
}

// round 3
// speedup vs baseline: 1.3540x; 1.3540x over previous
#include <cuda_runtime.h>

#define NN 100000
#define NE 1200000
#define D 64
#define NL 3
#define NG 256
#define RH 128
#define RO 32
#define INDIM (D*NL)   // 192
#define GR 64          // rows per GEMM block

typedef unsigned long long ull;

// ---------------- scratch (device globals; no allocation allowed) ----------
__device__ int   d_deg[NN];
__device__ int   d_rowptr[NN + 1];
__device__ int   d_cursor[NN];
__device__ int   d_col[NE];
__device__ int   d_bsum[128];
__device__ int   d_gstart[NG + 1];
__device__ float d_h0[NN * D];
__device__ float d_h1[NN * D];
__device__ float d_y[NN * D];
__device__ float d_g[NG * INDIM];

// ---------------- f32x2 helpers -------------------------------------------
static __device__ __forceinline__ ull pk2(float x, float y) {
    ull r; asm("mov.b64 %0, {%1, %2};" : "=l"(r) : "f"(x), "f"(y)); return r;
}
static __device__ __forceinline__ void upk2(ull v, float& x, float& y) {
    asm("mov.b64 {%0, %1}, %2;" : "=f"(x), "=f"(y) : "l"(v));
}
static __device__ __forceinline__ void ffma2(ull& c, ull a, ull b) {
    asm("fma.rn.f32x2 %0, %1, %2, %0;" : "+l"(c) : "l"(a), "l"(b));
}

// ---------------- CSR build ------------------------------------------------
__global__ void k_hist(const int* __restrict__ dst) {
    int e = blockIdx.x * blockDim.x + threadIdx.x;
    if (e < NE) atomicAdd(&d_deg[dst[e]], 1);
}

// CHUNK = 1024 elements per block, 256 threads x 4 items
__global__ void k_blocksum() {
    __shared__ int sh[256];
    int b = blockIdx.x, tid = threadIdx.x;
    int base = b * 1024 + tid * 4;
    int s = 0;
#pragma unroll
    for (int i = 0; i < 4; i++) {
        int idx = base + i;
        if (idx < NN) s += d_deg[idx];
    }
    sh[tid] = s;
    __syncthreads();
    for (int off = 128; off > 0; off >>= 1) {
        if (tid < off) sh[tid] += sh[tid + off];
        __syncthreads();
    }
    if (tid == 0) d_bsum[b] = sh[0];
}

// parallel exclusive scan of up to 128 block sums (one block, 128 threads)
__global__ void k_scan_bsum(int nb) {
    __shared__ int sh[128];
    int tid = threadIdx.x;
    int v = (tid < nb) ? d_bsum[tid] : 0;
    sh[tid] = v;
    __syncthreads();
    for (int off = 1; off < 128; off <<= 1) {
        int t = (tid >= off) ? sh[tid - off] : 0;
        __syncthreads();
        sh[tid] += t;
        __syncthreads();
    }
    if (tid < nb) d_bsum[tid] = sh[tid] - v;   // exclusive
    if (tid == 127) d_rowptr[NN] = sh[127];    // total (tail zeros don't matter)
}

__global__ void k_scanfinal() {
    __shared__ int sh[256];
    int b = blockIdx.x, tid = threadIdx.x;
    int base = b * 1024 + tid * 4;
    int v[4];
    int s = 0;
#pragma unroll
    for (int i = 0; i < 4; i++) {
        int idx = base + i;
        v[i] = (idx < NN) ? d_deg[idx] : 0;
        s += v[i];
    }
    sh[tid] = s;
    __syncthreads();
    for (int off = 1; off < 256; off <<= 1) {
        int t = 0;
        if (tid >= off) t = sh[tid - off];
        __syncthreads();
        if (tid >= off) sh[tid] += t;
        __syncthreads();
    }
    int run = d_bsum[b] + sh[tid] - s;
#pragma unroll
    for (int i = 0; i < 4; i++) {
        int idx = base + i;
        if (idx < NN) {
            d_rowptr[idx] = run;
            d_cursor[idx] = run;
            run += v[i];
        }
    }
}

__global__ void k_scatter(const int* __restrict__ src, const int* __restrict__ dst) {
    int e = blockIdx.x * blockDim.x + threadIdx.x;
    if (e < NE) {
        int dn = dst[e];
        int p = atomicAdd(&d_cursor[dn], 1);
        d_col[p] = src[e];
    }
}

__global__ void k_gstart(const int* __restrict__ gids) {
    int g = blockIdx.x * blockDim.x + threadIdx.x;
    if (g > NG) return;
    if (g == NG) { d_gstart[NG] = NN; return; }
    int lo = 0, hi = NN;
    while (lo < hi) {
        int mid = (lo + hi) >> 1;
        if (gids[mid] < g) lo = mid + 1; else hi = mid;
    }
    d_gstart[g] = lo;
}

// ---------------- dense GEMM: Y = Hin @ W[layer] ---------------------------
// Block: 256 threads, 64 rows. Thread t: dim pair dp=t&31 (dims 2dp,2dp+1),
// row group rg=t>>5 (rows rg*8..rg*8+7). Accumulate with fma.rn.f32x2 paired
// over k; W staged in smem and reused across 8 rows per thread.
__global__ void __launch_bounds__(256) k_gemm(
    const float* __restrict__ Hin, float* __restrict__ Y,
    const float* __restrict__ gin_W, int layer)
{
    __shared__ float4 Zs[GR][16];     // 64 rows x 64 floats (16 KB)
    __shared__ float2 Wsp[D][32];     // W[k][dp] pairs (16 KB)

    int tid = threadIdx.x;
    int row0 = blockIdx.x * GR;

    // stage W (1024 float4 total)
    const float4* Wg = (const float4*)(gin_W + layer * D * D);
    float4* Ws4 = (float4*)&Wsp[0][0];
#pragma unroll
    for (int i = 0; i < 4; i++) Ws4[tid + 256 * i] = Wg[tid + 256 * i];

    // stage rows (1024 float4)
    const float4* Hg = (const float4*)Hin;
#pragma unroll
    for (int i = 0; i < 4; i++) {
        int idx = tid + 256 * i;
        int r = row0 + (idx >> 4);
        int rc = (r < NN) ? r : (NN - 1);
        Zs[idx >> 4][idx & 15] = Hg[(size_t)rc * 16 + (idx & 15)];
    }
    __syncthreads();

    int dp = tid & 31;
    int rg = tid >> 5;

    ull accA[8], accB[8];
#pragma unroll
    for (int n = 0; n < 8; n++) { accA[n] = 0ull; accB[n] = 0ull; }

    for (int kc = 0; kc < D; kc += 16) {
        // repack W: wA[p] = (W[kc+2p][2dp], W[kc+2p+1][2dp]); wB same for 2dp+1
        ull wA[8], wB[8];
#pragma unroll
        for (int p = 0; p < 8; p++) {
            float2 lo = Wsp[kc + 2 * p][dp];
            float2 hi = Wsp[kc + 2 * p + 1][dp];
            wA[p] = pk2(lo.x, hi.x);
            wB[p] = pk2(lo.y, hi.y);
        }
#pragma unroll
        for (int n = 0; n < 8; n++) {
            const ull* zrowU = (const ull*)&Zs[rg * 8 + n][0];  // k-pairs
#pragma unroll
            for (int q = 0; q < 4; q++) {
                ull zA = zrowU[kc / 2 + 2 * q];
                ull zB = zrowU[kc / 2 + 2 * q + 1];
                ffma2(accA[n], wA[2 * q],     zA);
                ffma2(accB[n], wB[2 * q],     zA);
                ffma2(accA[n], wA[2 * q + 1], zB);
                ffma2(accB[n], wB[2 * q + 1], zB);
            }
        }
    }

#pragma unroll
    for (int n = 0; n < 8; n++) {
        int r = row0 + rg * 8 + n;
        if (r < NN) {
            float ax, ay, bx, by;
            upk2(accA[n], ax, ay);
            upk2(accB[n], bx, by);
            ((float2*)(Y + (size_t)r * D))[dp] = make_float2(ax + ay, bx + by);
        }
    }
}

// ---------------- aggregation: hout = relu((1+eps)Y_i + sum_nbr Y_j + b) ---
// warp per node, lane owns dims {2*lane, 2*lane+1}
__global__ void __launch_bounds__(256) k_agg(
    const float* __restrict__ Y, float* __restrict__ hout,
    const float* __restrict__ gin_b, const float* __restrict__ eps, int layer)
{
    int tid = threadIdx.x;
    int w = tid >> 5;
    int lane = tid & 31;
    int node = blockIdx.x * 8 + w;   // grid = NN/8 exactly

    float epsv = 1.0f + eps[layer];
    float2 b2 = ((const float2*)(gin_b + layer * D))[lane];

    float2 acc = ((const float2*)(Y + (size_t)node * D))[lane];
    acc.x *= epsv; acc.y *= epsv;

    int beg = d_rowptr[node], end = d_rowptr[node + 1];
    for (int e0 = beg; e0 < end; e0 += 32) {
        int idx = e0 + lane;
        int sn = (idx < end) ? d_col[idx] : 0;
        int cnt = min(32, end - e0);
        int j = 0;
        for (; j + 4 <= cnt; j += 4) {
            int s0 = __shfl_sync(0xffffffffu, sn, j + 0);
            int s1 = __shfl_sync(0xffffffffu, sn, j + 1);
            int s2 = __shfl_sync(0xffffffffu, sn, j + 2);
            int s3 = __shfl_sync(0xffffffffu, sn, j + 3);
            float2 v0 = ((const float2*)(Y + (size_t)s0 * D))[lane];
            float2 v1 = ((const float2*)(Y + (size_t)s1 * D))[lane];
            float2 v2 = ((const float2*)(Y + (size_t)s2 * D))[lane];
            float2 v3 = ((const float2*)(Y + (size_t)s3 * D))[lane];
            acc.x += v0.x + v1.x + v2.x + v3.x;
            acc.y += v0.y + v1.y + v2.y + v3.y;
        }
        for (; j < cnt; j++) {
            int sj = __shfl_sync(0xffffffffu, sn, j);
            float2 v = ((const float2*)(Y + (size_t)sj * D))[lane];
            acc.x += v.x; acc.y += v.y;
        }
    }

    float2 o;
    o.x = fmaxf(acc.x + b2.x, 0.0f);
    o.y = fmaxf(acc.y + b2.y, 0.0f);
    ((float2*)(hout + (size_t)node * D))[lane] = o;
}

// ---------------- per-graph segment sum (no atomics: gids sorted) ---------
__global__ void k_graph_accum(const float* __restrict__ h, int layer) {
    __shared__ float red[256];
    int b = blockIdx.x;
    int tid = threadIdx.x;
    int dim = tid & 63;
    int part = tid >> 6;
    int gs = d_gstart[b], ge = d_gstart[b + 1];
    float s = 0.0f;
    for (int i = gs + part; i < ge; i += 4)
        s += h[(size_t)i * D + dim];
    red[tid] = s;
    __syncthreads();
    if (part == 0) {
        float tot = red[dim] + red[64 + dim] + red[128 + dim] + red[192 + dim];
        d_g[b * INDIM + layer * D + dim] = tot;
    }
}

// ---------------- readout MLP ---------------------------------------------
__global__ void k_mlp(const float* __restrict__ W1, const float* __restrict__ b1,
                      const float* __restrict__ W2, const float* __restrict__ b2,
                      float* __restrict__ out)
{
    __shared__ float gv[INDIM];
    __shared__ float hid[RH];
    int b = blockIdx.x;
    int tid = threadIdx.x;   // 128 threads
    for (int i = tid; i < INDIM; i += RH) gv[i] = d_g[b * INDIM + i];
    __syncthreads();
    float a = b1[tid];
#pragma unroll 8
    for (int k = 0; k < INDIM; k++)
        a += gv[k] * W1[k * RH + tid];
    hid[tid] = fmaxf(a, 0.0f);
    __syncthreads();
    if (tid < RO) {
        float o = b2[tid];
#pragma unroll 8
        for (int k = 0; k < RH; k++)
            o += hid[k] * W2[k * RO + tid];
        out[b * RO + tid] = o;
    }
}

// ---------------- launch ---------------------------------------------------
extern "C" void kernel_launch(void* const* d_in, const int* in_sizes, int n_in,
                              void* d_out, int out_size)
{
    const float* x      = (const float*)d_in[0];
    const float* gin_W  = (const float*)d_in[1];
    const float* gin_b  = (const float*)d_in[2];
    const float* eps    = (const float*)d_in[3];
    const float* r_W1   = (const float*)d_in[4];
    const float* r_b1   = (const float*)d_in[5];
    const float* r_W2   = (const float*)d_in[6];
    const float* r_b2   = (const float*)d_in[7];
    const int*   src    = (const int*)d_in[8];
    const int*   dst    = (const int*)d_in[9];
    const int*   gids   = (const int*)d_in[10];
    float* out = (float*)d_out;

    const int NB_SCAN = (NN + 1023) / 1024;  // 98

    static float* h0p = nullptr;
    static float* h1p = nullptr;
    static float* yp  = nullptr;
    static int*   degp = nullptr;
    if (!h0p) {
        cudaGetSymbolAddress((void**)&h0p, d_h0);
        cudaGetSymbolAddress((void**)&h1p, d_h1);
        cudaGetSymbolAddress((void**)&yp,  d_y);
        cudaGetSymbolAddress((void**)&degp, d_deg);
    }

    // CSR build
    cudaMemsetAsync(degp, 0, NN * sizeof(int));
    k_hist<<<(NE + 255) / 256, 256>>>(dst);
    k_blocksum<<<NB_SCAN, 256>>>();
    k_scan_bsum<<<1, 128>>>(NB_SCAN);
    k_scanfinal<<<NB_SCAN, 256>>>();
    k_scatter<<<(NE + 255) / 256, 256>>>(src, dst);
    k_gstart<<<2, 256>>>(gids);

    // GIN layers: Y = Hin @ W (dense), then hout = relu((1+eps)Y + agg(Y) + b)
    const float* hin = x;
    float* bufs[2] = { h0p, h1p };
    for (int l = 0; l < NL; l++) {
        float* hout = bufs[l & 1];
        k_gemm<<<(NN + GR - 1) / GR, 256>>>(hin, yp, gin_W, l);
        k_agg<<<NN / 8, 256>>>(yp, hout, gin_b, eps, l);
        k_graph_accum<<<NG, 256>>>(hout, l);
        hin = hout;
    }

    // head MLP
    k_mlp<<<NG, RH>>>(r_W1, r_b1, r_W2, r_b2, out);
}